// round 14
// baseline (speedup 1.0000x reference)
#include <cuda_runtime.h>
#include <stdint.h>
#include <float.h>

// ChamferLoss2D: N=16, P=4096, D=2.
// cost_n = 0.5*(mean_i min_j C + mean_j min_i C), C = sqrt(clip(|x-y|^2, EPS))
// out = mean_n cost_n * (sum(set2_n) >= 0)
//
// Grid NN, exact, SMEM-resident (G=80: points 32KB + u16 cell table 12.8KB,
// static smem -- the proven-fastest configuration). Dense queries: 3x3
// row-run scalar scan. Tail: DIRECT-SIZED single rescan -- box computed from
// d = sqrt(best) in cell space covers every point that could beat best
// (clamping pulls in edge cells exactly when the interval reaches the domain
// edge, where outliers live) => exact for ANY input, at most one rescan.

#define N_BATCH 16
#define P 4096

#define G 80
#define CELLS (G * G)            // 6400
#define CS_PAD (CELLS + 2)

#define DOM_LO (-5.2f)
#define DOM_W  (10.4f)
#define CELL_W (DOM_W / (float)G)
#define INV_W  ((float)G / DOM_W)

#define EPS 1e-12f
#define OUT_WT (0.5f / (float)P / (float)N_BATCH)

__device__ float2   g_pts[2][N_BATCH][P];           // cell-sorted points
__device__ uint16_t g_cellstart[2][N_BATCH][CS_PAD];
__device__ float    g_mask[N_BATCH];

__device__ __forceinline__ int cell_coord(float v) {
    int c = (int)((v - DOM_LO) * INV_W);
    return min(max(c, 0), G - 1);
}

// ---- build: one block of 512 per (set, batch) -------------------------------
#define TPB_B 512
#define PPT_B (P / TPB_B)        // 8
#define CELLS_PADB 6656          // 512 * 13
#define CPT_B 13

__global__ void __launch_bounds__(TPB_B) build_kernel(
    const float* __restrict__ s1, const float* __restrict__ s2,
    float* __restrict__ out) {
    const int set = blockIdx.x >> 4;
    const int n   = blockIdx.x & 15;
    const float2* __restrict__ src =
        (const float2*)((set ? s2 : s1) + (size_t)n * P * 2);

    __shared__ uint32_t s_cnt[CELLS_PADB];
    __shared__ uint32_t s_wsum[TPB_B / 32];
    __shared__ float    s_red[TPB_B / 32];

    const int t = threadIdx.x;
    const int lane = t & 31, w = t >> 5;

#pragma unroll
    for (int k = 0; k < CPT_B; k++) s_cnt[k * TPB_B + t] = 0;
    __syncthreads();

    float2 pt[PPT_B];
    int    cid[PPT_B];
    float  msum = 0.0f;
#pragma unroll
    for (int k = 0; k < PPT_B; k++) {
        float2 p = src[k * TPB_B + t];
        pt[k] = p;
        cid[k] = cell_coord(p.y) * G + cell_coord(p.x);
        atomicAdd(&s_cnt[cid[k]], 1u);
        msum += p.x + p.y;
    }
    __syncthreads();

    uint32_t tot = 0;
#pragma unroll
    for (int c = 0; c < CPT_B; c++) tot += s_cnt[t * CPT_B + c];
    uint32_t inc = tot;
#pragma unroll
    for (int o = 1; o < 32; o <<= 1) {
        uint32_t v = __shfl_up_sync(0xffffffffu, inc, o);
        if (lane >= o) inc += v;
    }
    if (lane == 31) s_wsum[w] = inc;
    uint32_t excl = inc - tot;
    __syncthreads();
    uint32_t wbase = 0;
#pragma unroll
    for (int ww = 0; ww < TPB_B / 32; ww++) {
        uint32_t v = s_wsum[ww];
        if (ww < w) wbase += v;
    }
    uint32_t run = wbase + excl;
#pragma unroll
    for (int c = 0; c < CPT_B; c++) {
        uint32_t v = s_cnt[t * CPT_B + c];
        s_cnt[t * CPT_B + c] = run;
        run += v;
    }
    __syncthreads();

    uint16_t* __restrict__ gs = g_cellstart[set][n];
#pragma unroll
    for (int k = 0; k < CPT_B; k++) {
        int i = k * TPB_B + t;
        if (i < CS_PAD) gs[i] = (uint16_t)s_cnt[i];
    }
    __syncthreads();  // publish reads s_cnt before scatter mutates it

    float2* __restrict__ gp = g_pts[set][n];
#pragma unroll
    for (int k = 0; k < PPT_B; k++) {
        uint32_t pos = atomicAdd(&s_cnt[cid[k]], 1u);
        gp[pos] = pt[k];
    }

#pragma unroll
    for (int o = 16; o > 0; o >>= 1) msum += __shfl_down_sync(0xffffffffu, msum, o);
    if (lane == 0) s_red[w] = msum;
    __syncthreads();
    if (t == 0) {
        float a = 0.0f;
#pragma unroll
        for (int ww = 0; ww < TPB_B / 32; ww++) a += s_red[ww];
        if (set == 1) g_mask[n] = (a >= 0.0f) ? 1.0f : 0.0f;
        if (set == 0 && n == 0) out[0] = 0.0f;
    }
}

// ---- query ------------------------------------------------------------------
#define TPB 256

__device__ __forceinline__ float sqd(float2 q, float2 p) {
    float dx = q.x - p.x;
    float dy = q.y - p.y;
    return fmaf(dx, dx, dy * dy);
}

__device__ __forceinline__ void scan_run(
    const float2* pts, int s, int e, float2 q, float& best) {
    for (int idx = s; idx < e; idx++)
        best = fminf(best, sqd(q, pts[idx]));
}

__global__ void __launch_bounds__(TPB) query_kernel(float* __restrict__ out) {
    // blockIdx: [dir(2)][n(16)][chunk(16)]
    const int chunk = blockIdx.x & 15;
    const int n     = (blockIdx.x >> 4) & 15;
    const int dir   = blockIdx.x >> 8;
    const int dst   = 1 - dir;
    const int t     = threadIdx.x;
    const int lane  = t & 31;
    const int w     = t >> 5;

    __shared__ __align__(16) float2   s_pts[P];       // 32 KB
    __shared__ __align__(4)  uint16_t s_cs[CS_PAD];   // 12.8 KB
    __shared__ float s_red[TPB / 32];

    // Issue the query load first (independent of the copy below).
    const int qidx = (w * 16 + chunk) * 32 + lane;    // warp-shuffled balance
    const float2 q = g_pts[dir][n][qidx];

    // Copy destination structure into smem (L2 hits, coalesced).
    {
        const float4* gp4 = (const float4*)g_pts[dst][n];
        float4* sp4 = (float4*)s_pts;
#pragma unroll
        for (int k = 0; k < (P / 2) / TPB; k++)
            sp4[k * TPB + t] = gp4[k * TPB + t];
        const uint32_t* gc = (const uint32_t*)g_cellstart[dst][n];
        uint32_t* sc = (uint32_t*)s_cs;
        for (int i = t; i < CS_PAD / 2; i += TPB)
            sc[i] = gc[i];
    }

    const int cx = cell_coord(q.x);
    const int cy = cell_coord(q.y);

    __syncthreads();

    float best = FLT_MAX;

    // Fast path: 3x3 box as up-to-three contiguous row-runs.
    const int ilo0 = max(cx - 1, 0), ihi0 = min(cx + 1, G - 1);
    const int jlo0 = max(cy - 1, 0), jhi0 = min(cy + 1, G - 1);
    for (int j = jlo0; j <= jhi0; j++)
        scan_run(s_pts, s_cs[j * G + ilo0], s_cs[j * G + ihi0 + 1], q, best);

    // Tail: direct-sized single rescan. Box from d = sqrt(best) covers every
    // point that could beat best (cell_coord clamping pulls in edge cells
    // exactly when the reach crosses the domain edge). Empty 3x3 -> d huge
    // -> full-grid scan. At most ONE rescan; rescans idempotent.
    {
        float d = sqrtf(best);
        int ilo = cell_coord(q.x - d), ihi = cell_coord(q.x + d);
        int jlo = cell_coord(q.y - d), jhi = cell_coord(q.y + d);
        if (!(ilo >= ilo0 && ihi <= ihi0 && jlo >= jlo0 && jhi <= jhi0)) {
            for (int j = jlo; j <= jhi; j++)
                scan_run(s_pts, s_cs[j * G + ilo], s_cs[j * G + ihi + 1], q, best);
        }
    }

    float d = sqrtf(fmaxf(best, EPS));

    // Block reduce (all threads in block share (dir, n)).
#pragma unroll
    for (int o = 16; o > 0; o >>= 1) d += __shfl_down_sync(0xffffffffu, d, o);
    if (lane == 0) s_red[w] = d;
    __syncthreads();
    if (t == 0) {
        float a = 0.0f;
#pragma unroll
        for (int ww = 0; ww < TPB / 32; ww++) a += s_red[ww];
        atomicAdd(out, a * g_mask[n] * OUT_WT);
    }
}

extern "C" void kernel_launch(void* const* d_in, const int* in_sizes, int n_in,
                              void* d_out, int out_size) {
    const float* s1 = (const float*)d_in[0];  // point_set_1: [16,4096,2] f32
    const float* s2 = (const float*)d_in[1];  // point_set_2: [16,4096,2] f32
    float* out = (float*)d_out;

    build_kernel<<<2 * N_BATCH, TPB_B>>>(s1, s2, out);
    query_kernel<<<2 * N_BATCH * (P / TPB), TPB>>>(out);
}

// round 15
// speedup vs baseline: 2.8831x; 2.8831x over previous
#include <cuda_runtime.h>
#include <stdint.h>
#include <float.h>

// ChamferLoss2D: N=16, P=4096, D=2.
// cost_n = 0.5*(mean_i min_j C + mean_j min_i C), C = sqrt(clip(|x-y|^2, EPS))
// out = mean_n cost_n * (sum(set2_n) >= 0)
//
// Grid NN, exact. Points (32KB) SMEM-resident; cell-table bounds for the 3x3
// fast path are PREFETCHED from global (L2) before the copy/sync, so their
// latency hides behind the smem fill. Sparse tail: geometric box growth with
// need-cap (r' = min(2r, reach(best))), bounds from L2 (rare). Edge-aware
// lower bound (clamped sides => inf) => exact for ANY input.

#define N_BATCH 16
#define P 4096

#define G 80
#define CELLS (G * G)            // 6400
#define CS_PAD (CELLS + 2)

#define DOM_LO (-5.2f)
#define DOM_W  (10.4f)
#define CELL_W (DOM_W / (float)G)
#define INV_W  ((float)G / DOM_W)

#define EPS 1e-12f
#define OUT_WT (0.5f / (float)P / (float)N_BATCH)

__device__ float2   g_pts[2][N_BATCH][P];           // cell-sorted points
__device__ uint16_t g_cellstart[2][N_BATCH][CS_PAD];
__device__ float    g_mask[N_BATCH];

__device__ __forceinline__ int cell_coord(float v) {
    int c = (int)((v - DOM_LO) * INV_W);
    return min(max(c, 0), G - 1);
}

// ---- build: one block of 512 per (set, batch) -------------------------------
#define TPB_B 512
#define PPT_B (P / TPB_B)        // 8
#define CELLS_PADB 6656          // 512 * 13
#define CPT_B 13

__global__ void __launch_bounds__(TPB_B) build_kernel(
    const float* __restrict__ s1, const float* __restrict__ s2,
    float* __restrict__ out) {
    const int set = blockIdx.x >> 4;
    const int n   = blockIdx.x & 15;
    const float2* __restrict__ src =
        (const float2*)((set ? s2 : s1) + (size_t)n * P * 2);

    __shared__ uint32_t s_cnt[CELLS_PADB];
    __shared__ uint32_t s_wsum[TPB_B / 32];
    __shared__ float    s_red[TPB_B / 32];

    const int t = threadIdx.x;
    const int lane = t & 31, w = t >> 5;

#pragma unroll
    for (int k = 0; k < CPT_B; k++) s_cnt[k * TPB_B + t] = 0;
    __syncthreads();

    float2 pt[PPT_B];
    int    cid[PPT_B];
    float  msum = 0.0f;
#pragma unroll
    for (int k = 0; k < PPT_B; k++) {
        float2 p = src[k * TPB_B + t];
        pt[k] = p;
        cid[k] = cell_coord(p.y) * G + cell_coord(p.x);
        atomicAdd(&s_cnt[cid[k]], 1u);
        msum += p.x + p.y;
    }
    __syncthreads();

    uint32_t tot = 0;
#pragma unroll
    for (int c = 0; c < CPT_B; c++) tot += s_cnt[t * CPT_B + c];
    uint32_t inc = tot;
#pragma unroll
    for (int o = 1; o < 32; o <<= 1) {
        uint32_t v = __shfl_up_sync(0xffffffffu, inc, o);
        if (lane >= o) inc += v;
    }
    if (lane == 31) s_wsum[w] = inc;
    uint32_t excl = inc - tot;
    __syncthreads();
    uint32_t wbase = 0;
#pragma unroll
    for (int ww = 0; ww < TPB_B / 32; ww++) {
        uint32_t v = s_wsum[ww];
        if (ww < w) wbase += v;
    }
    uint32_t run = wbase + excl;
#pragma unroll
    for (int c = 0; c < CPT_B; c++) {
        uint32_t v = s_cnt[t * CPT_B + c];
        s_cnt[t * CPT_B + c] = run;
        run += v;
    }
    __syncthreads();

    uint16_t* __restrict__ gs = g_cellstart[set][n];
#pragma unroll
    for (int k = 0; k < CPT_B; k++) {
        int i = k * TPB_B + t;
        if (i < CS_PAD) gs[i] = (uint16_t)s_cnt[i];
    }
    __syncthreads();  // publish reads s_cnt before scatter mutates it

    float2* __restrict__ gp = g_pts[set][n];
#pragma unroll
    for (int k = 0; k < PPT_B; k++) {
        uint32_t pos = atomicAdd(&s_cnt[cid[k]], 1u);
        gp[pos] = pt[k];
    }

#pragma unroll
    for (int o = 16; o > 0; o >>= 1) msum += __shfl_down_sync(0xffffffffu, msum, o);
    if (lane == 0) s_red[w] = msum;
    __syncthreads();
    if (t == 0) {
        float a = 0.0f;
#pragma unroll
        for (int ww = 0; ww < TPB_B / 32; ww++) a += s_red[ww];
        if (set == 1) g_mask[n] = (a >= 0.0f) ? 1.0f : 0.0f;
        if (set == 0 && n == 0) out[0] = 0.0f;
    }
}

// ---- query ------------------------------------------------------------------
#define TPB 256

__device__ __forceinline__ float sqd(float2 q, float2 p) {
    float dx = q.x - p.x;
    float dy = q.y - p.y;
    return fmaf(dx, dx, dy * dy);
}

__device__ __forceinline__ void scan_run(
    const float2* pts, int s, int e, float2 q, float& best) {
    for (int idx = s; idx < e; idx++)
        best = fminf(best, sqd(q, pts[idx]));
}

// Lower bound to unscanned region outside box radius r; clamped sides => inf.
__device__ __forceinline__ float box_lb(float qx, float qy, int cx, int cy, int r) {
    float l  = (cx - r <= 0)     ? FLT_MAX : qx - (DOM_LO + (float)(cx - r) * CELL_W);
    float rt = (cx + r >= G - 1) ? FLT_MAX : (DOM_LO + (float)(cx + r + 1) * CELL_W) - qx;
    float b  = (cy - r <= 0)     ? FLT_MAX : qy - (DOM_LO + (float)(cy - r) * CELL_W);
    float tp = (cy + r >= G - 1) ? FLT_MAX : (DOM_LO + (float)(cy + r + 1) * CELL_W) - qy;
    return fminf(fminf(l, rt), fminf(b, tp));
}

__global__ void __launch_bounds__(TPB) query_kernel(float* __restrict__ out) {
    // blockIdx: [dir(2)][n(16)][chunk(16)]
    const int chunk = blockIdx.x & 15;
    const int n     = (blockIdx.x >> 4) & 15;
    const int dir   = blockIdx.x >> 8;
    const int dst   = 1 - dir;
    const int t     = threadIdx.x;
    const int lane  = t & 31;
    const int w     = t >> 5;

    __shared__ __align__(16) float2 s_pts[P];   // 32 KB (points only)
    __shared__ float s_red[TPB / 32];

    const uint16_t* __restrict__ gcs = g_cellstart[dst][n];

    // Query load + 3x3 bound prefetch (global/L2), issued BEFORE the copy so
    // their latency hides behind the smem fill.
    const int qidx = (w * 16 + chunk) * 32 + lane;    // warp-shuffled balance
    const float2 q = g_pts[dir][n][qidx];
    const int cx = cell_coord(q.x);
    const int cy = cell_coord(q.y);

    const int  ilo = max(cx - 1, 0), iw = min(cx + 1, G - 1) + 1;
    const bool v0 = cy > 0, v2 = cy < G - 1;
    const int  j0 = v0 ? cy - 1 : cy;
    const int  j2 = v2 ? cy + 1 : cy;
    int s0 = gcs[j0 * G + ilo], e0 = gcs[j0 * G + iw];
    int s1 = gcs[cy * G + ilo], e1 = gcs[cy * G + iw];
    int s2 = gcs[j2 * G + ilo], e2 = gcs[j2 * G + iw];
    if (!v0) e0 = s0;
    if (!v2) e2 = s2;

    // Copy destination points into smem (L2 hits, coalesced).
    {
        const float4* gp4 = (const float4*)g_pts[dst][n];
        float4* sp4 = (float4*)s_pts;
#pragma unroll
        for (int k = 0; k < (P / 2) / TPB; k++)
            sp4[k * TPB + t] = gp4[k * TPB + t];
    }
    __syncthreads();

    float best = FLT_MAX;

    // Fast path: 3x3 box, three prefetched row-runs, pure smem scanning.
    scan_run(s_pts, s0, e0, q, best);
    scan_run(s_pts, s1, e1, q, best);
    scan_run(s_pts, s2, e2, q, best);

    // Sparse tail: geometric box growth with need-cap; bounds from L2
    // (rare). Rescans idempotent; dense queries never get here.
    int r = 1;
    while (true) {
        float lb = box_lb(q.x, q.y, cx, cy, r);
        if (best <= lb * lb) break;       // inf^2 covers clamped/full coverage
        int rn = 2 * r;
        if (best < 1e30f) {               // finite best -> right-size the box
            int need = (int)(sqrtf(best) * INV_W) + 2;
            rn = min(rn, max(need, r + 1));
        }
        r = min(rn, G);
        int blo = max(cx - r, 0), bw = min(cx + r, G - 1) + 1;
        int jlo = max(cy - r, 0), jhi = min(cy + r, G - 1);
        for (int j = jlo; j <= jhi; j++)
            scan_run(s_pts, gcs[j * G + blo], gcs[j * G + bw], q, best);
    }

    float d = sqrtf(fmaxf(best, EPS));

    // Block reduce (all threads in block share (dir, n)).
#pragma unroll
    for (int o = 16; o > 0; o >>= 1) d += __shfl_down_sync(0xffffffffu, d, o);
    if (lane == 0) s_red[w] = d;
    __syncthreads();
    if (t == 0) {
        float a = 0.0f;
#pragma unroll
        for (int ww = 0; ww < TPB / 32; ww++) a += s_red[ww];
        atomicAdd(out, a * g_mask[n] * OUT_WT);
    }
}

extern "C" void kernel_launch(void* const* d_in, const int* in_sizes, int n_in,
                              void* d_out, int out_size) {
    const float* s1 = (const float*)d_in[0];  // point_set_1: [16,4096,2] f32
    const float* s2 = (const float*)d_in[1];  // point_set_2: [16,4096,2] f32
    float* out = (float*)d_out;

    build_kernel<<<2 * N_BATCH, TPB_B>>>(s1, s2, out);
    query_kernel<<<2 * N_BATCH * (P / TPB), TPB>>>(out);
}